// round 3
// baseline (speedup 1.0000x reference)
#include <cuda_runtime.h>

// ---------------------------------------------------------------------------
// WindowAttention (as written in the reference!):
//   xw  = window partition of x           [2048*49, 256]
//   qkv = xw @ w_qkv^T                    [2048*49, 768]  (3, NH=8, hd=32)
//   PER TOKEN: A[h,e] = q[h,:]·k[e,:] * 32^-0.5   (8x8, heads x heads!)
//              A = softmax(A, axis=e)
//              o[h,:] = sum_e A[h,e] * v[e,:]     (8x32)
//   out flatten: (n,s,h,d) -> swapaxes(1,2) -> per window h*1568 + s*32 + d
//   out = att @ w_proj^T + b, scattered back to (32,56,56,256)
// ---------------------------------------------------------------------------

#define M_TOK 100352     // 2048 windows * 49 tokens
#define KDIM  256
#define QKV_N 768

// Scratch (allocation-free rule: __device__ globals)
__device__ float g_qkv[(size_t)M_TOK * QKV_N];   // 308 MB
__device__ float g_att[(size_t)M_TOK * KDIM];    // 103 MB

// token row n -> element offset of (b, hh, wc, 0) in x / out
__device__ __forceinline__ int row_offset(int n) {
    int w  = n / 49;
    int s  = n - w * 49;
    int b  = w >> 6;           // 64 windows per batch (8x8)
    int wh = (w >> 3) & 7;
    int ww = w & 7;
    int r  = s / 7;
    int cc = s - r * 7;
    int hh = wh * 7 + r;
    int wc = ww * 7 + cc;
    return ((b * 56 + hh) * 56 + wc) * 256;
}

// ---------------------------------------------------------------------------
// Tiled SGEMM: C[M x NTOT] = A[M x 256] * B[NTOT x 256]^T  (K = 256)
// ---------------------------------------------------------------------------
#define BM 128
#define BN 128
#define BK 16

template<int NTOT, bool GATHER_A, bool SCATTER_OUT>
__global__ __launch_bounds__(256, 2)
void gemm_kernel(const float* __restrict__ A, const float* __restrict__ B,
                 const float* __restrict__ bias, float* __restrict__ Cout)
{
    __shared__ float As[BK][BM];
    __shared__ float Bs[BK][BN];

    const int tid = threadIdx.x;
    const int tx  = tid & 15;
    const int ty  = tid >> 4;

    const int m0 = blockIdx.y * BM;
    const int n0 = blockIdx.x * BN;

    const int lr  = tid >> 2;          // 0..63
    const int lc4 = (tid & 3) * 4;     // 0,4,8,12

    int a_off0, a_off1;
    if (GATHER_A) {
        a_off0 = row_offset(m0 + lr);
        a_off1 = row_offset(m0 + lr + 64);
    } else {
        a_off0 = (m0 + lr) * KDIM;
        a_off1 = (m0 + lr + 64) * KDIM;
    }
    const int b_off0 = (n0 + lr) * KDIM;
    const int b_off1 = (n0 + lr + 64) * KDIM;

    float acc[8][8];
    #pragma unroll
    for (int i = 0; i < 8; i++)
        #pragma unroll
        for (int j = 0; j < 8; j++) acc[i][j] = 0.f;

    for (int k0 = 0; k0 < KDIM; k0 += BK) {
        float4 av0 = *(const float4*)(A + a_off0 + k0 + lc4);
        float4 av1 = *(const float4*)(A + a_off1 + k0 + lc4);
        float4 bv0 = *(const float4*)(B + b_off0 + k0 + lc4);
        float4 bv1 = *(const float4*)(B + b_off1 + k0 + lc4);

        As[lc4 + 0][lr]      = av0.x;
        As[lc4 + 1][lr]      = av0.y;
        As[lc4 + 2][lr]      = av0.z;
        As[lc4 + 3][lr]      = av0.w;
        As[lc4 + 0][lr + 64] = av1.x;
        As[lc4 + 1][lr + 64] = av1.y;
        As[lc4 + 2][lr + 64] = av1.z;
        As[lc4 + 3][lr + 64] = av1.w;

        Bs[lc4 + 0][lr]      = bv0.x;
        Bs[lc4 + 1][lr]      = bv0.y;
        Bs[lc4 + 2][lr]      = bv0.z;
        Bs[lc4 + 3][lr]      = bv0.w;
        Bs[lc4 + 0][lr + 64] = bv1.x;
        Bs[lc4 + 1][lr + 64] = bv1.y;
        Bs[lc4 + 2][lr + 64] = bv1.z;
        Bs[lc4 + 3][lr + 64] = bv1.w;

        __syncthreads();

        #pragma unroll
        for (int k = 0; k < BK; k++) {
            float ra[8], rb[8];
            *(float4*)&ra[0] = *(const float4*)&As[k][ty * 8];
            *(float4*)&ra[4] = *(const float4*)&As[k][ty * 8 + 4];
            *(float4*)&rb[0] = *(const float4*)&Bs[k][tx * 8];
            *(float4*)&rb[4] = *(const float4*)&Bs[k][tx * 8 + 4];
            #pragma unroll
            for (int i = 0; i < 8; i++)
                #pragma unroll
                for (int j = 0; j < 8; j++)
                    acc[i][j] += ra[i] * rb[j];
        }
        __syncthreads();
    }

    const int colb = n0 + tx * 8;
    float bj[8];
    if (SCATTER_OUT) {
        #pragma unroll
        for (int j = 0; j < 8; j++) bj[j] = bias[colb + j];
    }
    #pragma unroll
    for (int i = 0; i < 8; i++) {
        const int m = m0 + ty * 8 + i;
        if (SCATTER_OUT) {
            const int base = row_offset(m);
            #pragma unroll
            for (int j = 0; j < 8; j += 4) {
                float4 v;
                v.x = acc[i][j + 0] + bj[j + 0];
                v.y = acc[i][j + 1] + bj[j + 1];
                v.z = acc[i][j + 2] + bj[j + 2];
                v.w = acc[i][j + 3] + bj[j + 3];
                *(float4*)(Cout + base + colb + j) = v;
            }
        } else {
            const int base = m * NTOT;
            #pragma unroll
            for (int j = 0; j < 8; j += 4) {
                float4 v;
                v.x = acc[i][j + 0];
                v.y = acc[i][j + 1];
                v.z = acc[i][j + 2];
                v.w = acc[i][j + 3];
                *(float4*)(Cout + base + colb + j) = v;
            }
        }
    }
}

// ---------------------------------------------------------------------------
// Per-token head-mixing attention: A = softmax_e(q_h . k_e / sqrt(32)),
// o[h,:] = sum_e A[h,e] v[e,:].
// 112 threads = 14 tokens x 8 heads. qkv rows staged in smem (pad 776).
// ---------------------------------------------------------------------------
#define ATT_TOK 14
#define ATT_THREADS (ATT_TOK * 8)

__global__ __launch_bounds__(ATT_THREADS)
void attn_kernel(const float* __restrict__ qkv, float* __restrict__ att)
{
    __shared__ float rows[ATT_TOK][776];

    const int tid  = threadIdx.x;
    const int tok0 = blockIdx.x * ATT_TOK;

    // stage 14 x 768 floats (float4), 24 loads per thread
    for (int i = tid; i < ATT_TOK * 192; i += ATT_THREADS) {
        int t = i / 192, c4 = (i - t * 192) * 4;
        *(float4*)&rows[t][c4] =
            *(const float4*)(qkv + (size_t)(tok0 + t) * QKV_N + c4);
    }
    __syncthreads();

    const int t = tid >> 3;     // token within block
    const int h = tid & 7;      // head (query head)
    const float* row = rows[t];

    float q[32];
    #pragma unroll
    for (int d = 0; d < 32; d++) q[d] = row[h * 32 + d];

    const float scale = 0.17677669529663687f;   // 1/sqrt(32)
    float a[8];
    #pragma unroll
    for (int e = 0; e < 8; e++) {
        float acc = 0.f;
        #pragma unroll
        for (int d = 0; d < 32; d++) acc += q[d] * row[256 + e * 32 + d];
        a[e] = acc * scale;
    }

    float mx = a[0];
    #pragma unroll
    for (int e = 1; e < 8; e++) mx = fmaxf(mx, a[e]);
    float sum = 0.f;
    #pragma unroll
    for (int e = 0; e < 8; e++) { a[e] = __expf(a[e] - mx); sum += a[e]; }
    float inv = 1.f / sum;
    #pragma unroll
    for (int e = 0; e < 8; e++) a[e] *= inv;

    // output: (n,s,h,d) swapaxes(1,2) flatten -> w*12544 + h*1568 + s*32 + d
    const int n = tok0 + t;
    const int w = n / 49;
    const int s = n - w * 49;
    float* op = att + (size_t)w * 12544 + h * 1568 + s * 32;

    #pragma unroll
    for (int d = 0; d < 32; d += 4) {
        float4 o;
        o.x = o.y = o.z = o.w = 0.f;
        #pragma unroll
        for (int e = 0; e < 8; e++) {
            const float* vp = &row[512 + e * 32 + d];
            o.x += a[e] * vp[0];
            o.y += a[e] * vp[1];
            o.z += a[e] * vp[2];
            o.w += a[e] * vp[3];
        }
        *(float4*)(op + d) = o;
    }
}

// ---------------------------------------------------------------------------
extern "C" void kernel_launch(void* const* d_in, const int* in_sizes, int n_in,
                              void* d_out, int out_size)
{
    (void)in_sizes; (void)n_in; (void)out_size;
    const float* x      = (const float*)d_in[0];
    const float* w_qkv  = (const float*)d_in[1];
    const float* w_proj = (const float*)d_in[2];
    const float* b_proj = (const float*)d_in[3];
    float* out = (float*)d_out;

    void* qkv_ptr = nullptr;
    void* att_ptr = nullptr;
    cudaGetSymbolAddress(&qkv_ptr, g_qkv);
    cudaGetSymbolAddress(&att_ptr, g_att);
    float* qkv = (float*)qkv_ptr;
    float* att = (float*)att_ptr;

    // 1) QKV projection with fused window gather on A
    {
        dim3 grid(QKV_N / BN, M_TOK / BM);   // (6, 784)
        gemm_kernel<QKV_N, true, false><<<grid, 256>>>(x, w_qkv, nullptr, qkv);
    }
    // 2) per-token head-mixing attention (M_TOK / 14 = 7168 blocks)
    {
        attn_kernel<<<M_TOK / ATT_TOK, ATT_THREADS>>>(qkv, att);
    }
    // 3) output projection + bias with fused window scatter
    {
        dim3 grid(KDIM / BN, M_TOK / BM);    // (2, 784)
        gemm_kernel<KDIM, false, true><<<grid, 256>>>(att, w_proj, b_proj, out);
    }
}

// round 4
// speedup vs baseline: 2.1563x; 2.1563x over previous
#include <cuda_runtime.h>
#include <cstdint>

// ---------------------------------------------------------------------------
// WindowAttention (reference semantics):
//   qkv = window_gather(x) @ w_qkv^T          [100352 x 768]
//   per token: A[h,e] = softmax_e(q_h . k_e / sqrt(32));  o_h = sum_e A[h,e] v_e
//   att layout per window: h*1568 + s*32 + d  (swapaxes(1,2) flatten)
//   out = att @ w_proj^T + b, window-scattered back to (32,56,56,256)
// ---------------------------------------------------------------------------

#define M_TOK 100352
#define KDIM  256
#define QKV_N 768

__device__ float g_qkv[(size_t)M_TOK * QKV_N];
__device__ float g_att[(size_t)M_TOK * KDIM];

__device__ __forceinline__ int row_offset(int n) {
    int w  = n / 49;
    int s  = n - w * 49;
    int b  = w >> 6;
    int wh = (w >> 3) & 7;
    int ww = w & 7;
    int r  = s / 7;
    int cc = s - r * 7;
    int hh = wh * 7 + r;
    int wc = ww * 7 + cc;
    return ((b * 56 + hh) * 56 + wc) * 256;
}

// ---------------------------------------------------------------------------
// tf32 tensor-core GEMM: C[M x NTOT] = A[M x 256] * B[NTOT x 256]^T
// 128x128 tile, BK=32, 256 thr, 8 warps x (64x32), mma.m16n8k8.tf32.
// smem row-major, 36-float row pad -> conflict-free fragment lds.
// cp.async double-buffered.
// ---------------------------------------------------------------------------
#define TBM 128
#define TBN 128
#define TBK 32
#define LDS 36
#define ABUF (128 * LDS)          // floats per A buffer
#define SMEM_FLOATS (4 * ABUF)    // A0,A1,B0,B1
#define SMEM_BYTES (SMEM_FLOATS * 4)

__device__ __forceinline__ uint32_t f2tf(float f) {
    uint32_t u;
    asm("cvt.rna.tf32.f32 %0, %1;" : "=r"(u) : "f"(f));
    return u;
}
__device__ __forceinline__ void cpa16(void* s, const void* g) {
    uint32_t sa = (uint32_t)__cvta_generic_to_shared(s);
    asm volatile("cp.async.cg.shared.global [%0], [%1], 16;" :: "r"(sa), "l"(g));
}
__device__ __forceinline__ void mma_tf32(float c[4], const uint32_t a[4], const uint32_t b[2]) {
    asm volatile(
        "mma.sync.aligned.m16n8k8.row.col.f32.tf32.tf32.f32 "
        "{%0,%1,%2,%3}, {%4,%5,%6,%7}, {%8,%9}, {%0,%1,%2,%3};"
        : "+f"(c[0]), "+f"(c[1]), "+f"(c[2]), "+f"(c[3])
        : "r"(a[0]), "r"(a[1]), "r"(a[2]), "r"(a[3]), "r"(b[0]), "r"(b[1]));
}

template<int NTOT, bool GATHER_A, bool SCATTER_OUT>
__global__ __launch_bounds__(256)
void gemm_tc(const float* __restrict__ A, const float* __restrict__ B,
             const float* __restrict__ bias, float* __restrict__ Cout)
{
    extern __shared__ float sm[];
    float* Asm = sm;               // [2][128][36]
    float* Bsm = sm + 2 * ABUF;    // [2][128][36]

    const int tid  = threadIdx.x;
    const int lane = tid & 31;
    const int warp = tid >> 5;
    const int wm = (warp & 1) * 64;
    const int wn = (warp >> 1) * 32;
    const int g  = lane >> 2;
    const int q  = lane & 3;

    const int m0 = blockIdx.y * TBM;
    const int n0 = blockIdx.x * TBN;

    // loader: thread -> (row, 16-float half)
    const int lrow  = tid >> 1;
    const int lhalf = (tid & 1) * 16;
    const long a_base = GATHER_A ? (long)row_offset(m0 + lrow)
                                 : (long)(m0 + lrow) * KDIM;
    const long b_base = (long)(n0 + lrow) * KDIM;

    float acc[4][4][4];
    #pragma unroll
    for (int i = 0; i < 4; i++)
        #pragma unroll
        for (int j = 0; j < 4; j++)
            #pragma unroll
            for (int c = 0; c < 4; c++) acc[i][j][c] = 0.f;

    auto stage = [&](int buf, int k0) {
        float* as = Asm + buf * ABUF + lrow * LDS + lhalf;
        float* bs = Bsm + buf * ABUF + lrow * LDS + lhalf;
        const float* ag = A + a_base + k0 + lhalf;
        const float* bg = B + b_base + k0 + lhalf;
        #pragma unroll
        for (int i = 0; i < 4; i++) {
            cpa16(as + i * 4, ag + i * 4);
            cpa16(bs + i * 4, bg + i * 4);
        }
    };

    stage(0, 0);
    asm volatile("cp.async.commit_group;");

    const int NT = KDIM / TBK;   // 8
    #pragma unroll 1
    for (int t = 0; t < NT; ++t) {
        if (t + 1 < NT) {
            stage((t + 1) & 1, (t + 1) * TBK);
            asm volatile("cp.async.commit_group;");
            asm volatile("cp.async.wait_group 1;");
        } else {
            asm volatile("cp.async.wait_group 0;");
        }
        __syncthreads();

        const float* as = Asm + (t & 1) * ABUF;
        const float* bs = Bsm + (t & 1) * ABUF;
        #pragma unroll
        for (int kk = 0; kk < 4; kk++) {
            const int k8 = kk * 8;
            uint32_t af[4][4], bf[4][2];
            #pragma unroll
            for (int mt = 0; mt < 4; mt++) {
                const float* p = as + (wm + mt * 16 + g) * LDS + k8 + q;
                af[mt][0] = f2tf(p[0]);
                af[mt][1] = f2tf(p[8 * LDS]);
                af[mt][2] = f2tf(p[4]);
                af[mt][3] = f2tf(p[8 * LDS + 4]);
            }
            #pragma unroll
            for (int nt = 0; nt < 4; nt++) {
                const float* p = bs + (wn + nt * 8 + g) * LDS + k8 + q;
                bf[nt][0] = f2tf(p[0]);
                bf[nt][1] = f2tf(p[4]);
            }
            #pragma unroll
            for (int mt = 0; mt < 4; mt++)
                #pragma unroll
                for (int nt = 0; nt < 4; nt++)
                    mma_tf32(acc[mt][nt], af[mt], bf[nt]);
        }
        __syncthreads();
    }

    // epilogue: per (mt) two rows (g, g+8); per (nt) a float2 at col 2q
    #pragma unroll
    for (int mt = 0; mt < 4; mt++) {
        #pragma unroll
        for (int ri = 0; ri < 2; ri++) {
            const int m = m0 + wm + mt * 16 + g + ri * 8;
            const long obase = SCATTER_OUT ? (long)row_offset(m) : (long)m * NTOT;
            #pragma unroll
            for (int nt = 0; nt < 4; nt++) {
                const int col = n0 + wn + nt * 8 + 2 * q;
                float2 v;
                v.x = acc[mt][nt][ri * 2 + 0];
                v.y = acc[mt][nt][ri * 2 + 1];
                if (SCATTER_OUT) {
                    v.x += bias[col];
                    v.y += bias[col + 1];
                }
                *(float2*)(Cout + obase + col) = v;
            }
        }
    }
}

// ---------------------------------------------------------------------------
// Per-token head-mixing attention (8x8 over heads), fp32.
// ---------------------------------------------------------------------------
#define ATT_TOK 14
#define ATT_THREADS (ATT_TOK * 8)

__global__ __launch_bounds__(ATT_THREADS)
void attn_kernel(const float* __restrict__ qkv, float* __restrict__ att)
{
    __shared__ float rows[ATT_TOK][776];

    const int tid  = threadIdx.x;
    const int tok0 = blockIdx.x * ATT_TOK;

    for (int i = tid; i < ATT_TOK * 192; i += ATT_THREADS) {
        int t = i / 192, c4 = (i - t * 192) * 4;
        *(float4*)&rows[t][c4] =
            *(const float4*)(qkv + (size_t)(tok0 + t) * QKV_N + c4);
    }
    __syncthreads();

    const int t = tid >> 3;
    const int h = tid & 7;
    const float* row = rows[t];

    float qv[32];
    #pragma unroll
    for (int d = 0; d < 32; d++) qv[d] = row[h * 32 + d];

    const float scale = 0.17677669529663687f;
    float a[8];
    #pragma unroll
    for (int e = 0; e < 8; e++) {
        float acc = 0.f;
        #pragma unroll
        for (int d = 0; d < 32; d++) acc += qv[d] * row[256 + e * 32 + d];
        a[e] = acc * scale;
    }

    float mx = a[0];
    #pragma unroll
    for (int e = 1; e < 8; e++) mx = fmaxf(mx, a[e]);
    float sum = 0.f;
    #pragma unroll
    for (int e = 0; e < 8; e++) { a[e] = __expf(a[e] - mx); sum += a[e]; }
    float inv = 1.f / sum;
    #pragma unroll
    for (int e = 0; e < 8; e++) a[e] *= inv;

    const int n = tok0 + t;
    const int w = n / 49;
    const int s = n - w * 49;
    float* op = att + (size_t)w * 12544 + h * 1568 + s * 32;

    #pragma unroll
    for (int d = 0; d < 32; d += 4) {
        float4 o;
        o.x = o.y = o.z = o.w = 0.f;
        #pragma unroll
        for (int e = 0; e < 8; e++) {
            const float* vp = &row[512 + e * 32 + d];
            o.x += a[e] * vp[0];
            o.y += a[e] * vp[1];
            o.z += a[e] * vp[2];
            o.w += a[e] * vp[3];
        }
        *(float4*)(op + d) = o;
    }
}

// ---------------------------------------------------------------------------
extern "C" void kernel_launch(void* const* d_in, const int* in_sizes, int n_in,
                              void* d_out, int out_size)
{
    (void)in_sizes; (void)n_in; (void)out_size;
    const float* x      = (const float*)d_in[0];
    const float* w_qkv  = (const float*)d_in[1];
    const float* w_proj = (const float*)d_in[2];
    const float* b_proj = (const float*)d_in[3];
    float* out = (float*)d_out;

    void* qkv_ptr = nullptr;
    void* att_ptr = nullptr;
    cudaGetSymbolAddress(&qkv_ptr, g_qkv);
    cudaGetSymbolAddress(&att_ptr, g_att);
    float* qkv = (float*)qkv_ptr;
    float* att = (float*)att_ptr;

    static bool attr_done = false;
    if (!attr_done) {
        cudaFuncSetAttribute(gemm_tc<QKV_N, true, false>,
                             cudaFuncAttributeMaxDynamicSharedMemorySize, SMEM_BYTES);
        cudaFuncSetAttribute(gemm_tc<KDIM, false, true>,
                             cudaFuncAttributeMaxDynamicSharedMemorySize, SMEM_BYTES);
        attr_done = true;
    }

    {
        dim3 grid(QKV_N / TBN, M_TOK / TBM);   // (6, 784)
        gemm_tc<QKV_N, true, false><<<grid, 256, SMEM_BYTES>>>(x, w_qkv, nullptr, qkv);
    }
    {
        attn_kernel<<<M_TOK / ATT_TOK, ATT_THREADS>>>(qkv, att);
    }
    {
        dim3 grid(KDIM / TBN, M_TOK / TBM);    // (2, 784)
        gemm_tc<KDIM, false, true><<<grid, 256, SMEM_BYTES>>>(att, w_proj, b_proj, out);
    }
}